// round 9
// baseline (speedup 1.0000x reference)
#include <cuda_runtime.h>
#include <cfloat>

#define NCOLS 1000
#define NVEC  250          // float4s per row per array
#define TPB   64
#define NWARP (TPB / 32)   // 2
#define TAIL_VALID (NVEC - 3 * TPB)   // 58
#define NSM   152
#define CTAS_PER_SM 17
#define NBLK  (NSM * CTAS_PER_SM)     // 2584

// Order-preserving float<->uint mapping
__device__ __forceinline__ unsigned ford(float f) {
    unsigned u = __float_as_uint(f);
    return ((int)u < 0) ? ~u : (u | 0x80000000u);
}
__device__ __forceinline__ float funord(unsigned u) {
    return __uint_as_float(((int)u < 0) ? (u ^ 0x80000000u) : ~u);
}

// Exact warp top-2 in ordered-uint domain (per-lane o1 >= o2 on entry).
__device__ __forceinline__ void warp_top2(unsigned& o1, unsigned& o2) {
    unsigned r1  = __reduce_max_sync(0xFFFFFFFFu, o1);
    unsigned bal = __ballot_sync(0xFFFFFFFFu, o1 == r1);
    unsigned u   = (o1 == r1) ? o2 : o1;
    unsigned r2  = __reduce_max_sync(0xFFFFFFFFu, u);
    if (__popc(bal) > 1) r2 = r1;   // duplicated max across lanes -> t2 == t1
    o1 = r1; o2 = r2;
}

// Branchless exact top-2 of 8 (FMNMX tournament)
__device__ __forceinline__ void top2_8(const float* v, float& t1, float& t2) {
    float m0 = fmaxf(v[0], v[1]), n0 = fminf(v[0], v[1]);
    float m1 = fmaxf(v[2], v[3]), n1 = fminf(v[2], v[3]);
    float m2 = fmaxf(v[4], v[5]), n2 = fminf(v[4], v[5]);
    float m3 = fmaxf(v[6], v[7]), n3 = fminf(v[6], v[7]);
    float a1 = fmaxf(m0, m1), a2 = fmaxf(fminf(m0, m1), fmaxf(n0, n1));
    float b1 = fmaxf(m2, m3), b2 = fmaxf(fminf(m2, m3), fmaxf(n2, n3));
    t1 = fmaxf(a1, b1);
    t2 = fmaxf(fminf(a1, b1), fmaxf(a2, b2));
}

// Merge (t1,t2) <- top2 of union with (q1,q2)
__device__ __forceinline__ void pair_merge(float& t1, float& t2, float q1, float q2) {
    float mn = fminf(t1, q1);
    t1 = fmaxf(t1, q1);
    t2 = fmaxf(mn, fmaxf(t2, q2));
}

__device__ __forceinline__ void top2_16(const float* v, float& t1, float& t2) {
    float p1, p2, q1, q2;
    top2_8(v, p1, p2);
    top2_8(v + 8, q1, q2);
    pair_merge(p1, p2, q1, q2);
    t1 = p1; t2 = p2;
}

__device__ __forceinline__ void l2_prefetch(const void* p) {
    asm volatile("prefetch.global.L2 [%0];" :: "l"(p));
}

__global__ __launch_bounds__(TPB, 12)
void netsat1_kernel(const float* __restrict__ y1,
                    const float* __restrict__ y2,
                    float* __restrict__ out,
                    int B)
{
    const int t   = threadIdx.x;
    const int wid = t >> 5;
    const int lid = t & 31;

    const bool tv = (t < TAIL_VALID);
    const int idx3base = tv ? 3 * TPB : 0;   // clamped chunk offset (masked later)

    __shared__ float4 sw[NWARP];
    __shared__ unsigned smax[NWARP];

    for (int row = blockIdx.x; row < B; row += NBLK) {
        const float4* r1 = reinterpret_cast<const float4*>(y1 + (size_t)row * NCOLS);
        const float4* r2 = reinterpret_cast<const float4*>(y2 + (size_t)row * NCOLS);

        // Front-batched loads for this row (all unconditional; tail clamped+masked)
        float4 v0 = __ldcs(&r1[t]);
        float4 v1 = __ldcs(&r1[t + TPB]);
        float4 v2 = __ldcs(&r1[t + 2 * TPB]);
        float4 v3 = __ldcs(&r1[t + idx3base]);
        float4 w0 = __ldcs(&r2[t]);
        float4 w1 = __ldcs(&r2[t + TPB]);
        float4 w2 = __ldcs(&r2[t + 2 * TPB]);
        float4 w3 = __ldcs(&r2[t + idx3base]);

        // L2-prefetch the next row while this row's loads are in flight
        const int nrow = row + NBLK;
        if (nrow < B) {
            const float* p1 = y1 + (size_t)nrow * NCOLS;
            const float* p2 = y2 + (size_t)nrow * NCOLS;
            // 4 KB per array; 32 lanes x 128B = 4 KB per prefetch sweep
            l2_prefetch(p1 + lid * 32);
            l2_prefetch(p1 + 1024 + lid * 32);   // lanes cover [0,4096) bytes in 128B steps
            l2_prefetch(p2 + lid * 32);
            l2_prefetch(p2 + 1024 + lid * 32);
        }

        float a[16], b[16];
        a[0]=v0.x; a[1]=v0.y; a[2]=v0.z; a[3]=v0.w;
        a[4]=v1.x; a[5]=v1.y; a[6]=v1.z; a[7]=v1.w;
        a[8]=v2.x; a[9]=v2.y; a[10]=v2.z; a[11]=v2.w;
        a[12] = tv ? v3.x : -FLT_MAX;  a[13] = tv ? v3.y : -FLT_MAX;
        a[14] = tv ? v3.z : -FLT_MAX;  a[15] = tv ? v3.w : -FLT_MAX;
        b[0]=w0.x; b[1]=w0.y; b[2]=w0.z; b[3]=w0.w;
        b[4]=w1.x; b[5]=w1.y; b[6]=w1.z; b[7]=w1.w;
        b[8]=w2.x; b[9]=w2.y; b[10]=w2.z; b[11]=w2.w;
        b[12] = tv ? w3.x : -FLT_MAX;  b[13] = tv ? w3.y : -FLT_MAX;
        b[14] = tv ? w3.z : -FLT_MAX;  b[15] = tv ? w3.w : -FLT_MAX;

        // --- Pass 1: per-thread exact top-2 of 16, then warp top-2 ---
        float ta1, ta2, tb1, tb2;
        top2_16(a, ta1, ta2);
        top2_16(b, tb1, tb2);

        unsigned oa1 = ford(ta1), oa2 = ford(ta2);
        unsigned ob1 = ford(tb1), ob2 = ford(tb2);
        warp_top2(oa1, oa2);
        warp_top2(ob1, ob2);

        if (lid == 0)
            sw[wid] = make_float4(funord(oa1), funord(oa2), funord(ob1), funord(ob2));
        __syncthreads();

        float4 s0 = sw[0], s1 = sw[1];
        float t1_1 = s0.x, t2_1 = s0.y, t1_2 = s0.z, t2_2 = s0.w;
        pair_merge(t1_1, t2_1, s1.x, s1.y);
        pair_merge(t1_2, t2_2, s1.z, s1.w);

        // --- Pass 2 (registers), shifted domain:
        // min(y1-t1_1, y2-t1_2) = min(y1, y2 + d) - t1_1,  d = t1_1 - t1_2
        const float d = t1_1 - t1_2;
        float m = -FLT_MAX;
        #pragma unroll
        for (int k = 0; k < 16; ++k)
            m = fmaxf(m, fminf(a[k], b[k] + d));

        // Fixup iff this thread holds a row-argmax element of either array (cold).
        if ((ta1 == t1_1) || (tb1 == t1_2)) {
            #pragma unroll
            for (int k = 0; k < 16; ++k) {
                if (a[k] == t1_1 || b[k] == t1_2) {
                    float loo1 = (a[k] == t1_1) ? t2_1 : t1_1;
                    float loo2 = (b[k] == t1_2) ? t2_2 : t1_2;
                    m = fmaxf(m, fminf(a[k] - loo1, b[k] - loo2) + t1_1);  // shifted
                }
            }
        }

        // --- Block max reduce of m (2 warps) ---
        unsigned om = __reduce_max_sync(0xFFFFFFFFu, ford(m));
        if (lid == 0) smax[wid] = om;
        __syncthreads();
        if (t == 0)
            out[row] = funord(max(smax[0], smax[1])) - t1_1;   // un-shift
        __syncthreads();   // protect sw/smax before next iteration overwrites
    }
}

extern "C" void kernel_launch(void* const* d_in, const int* in_sizes, int n_in,
                              void* d_out, int out_size)
{
    const float* y1 = (const float*)d_in[0];
    const float* y2 = (const float*)d_in[1];
    float* out = (float*)d_out;

    const int B = in_sizes[0] / NCOLS;   // 16384
    netsat1_kernel<<<NBLK, TPB>>>(y1, y2, out, B);
}

// round 10
// speedup vs baseline: 1.3481x; 1.3481x over previous
#include <cuda_runtime.h>
#include <cfloat>

#define NCOLS 1000
#define NVEC  250          // float4s per row per array
#define TPB   64
#define NWARP (TPB / 32)   // 2

// Order-preserving float<->uint mapping
__device__ __forceinline__ unsigned ford(float f) {
    unsigned u = __float_as_uint(f);
    return ((int)u < 0) ? ~u : (u | 0x80000000u);
}
__device__ __forceinline__ float funord(unsigned u) {
    return __uint_as_float(((int)u < 0) ? (u ^ 0x80000000u) : ~u);
}

// Exact warp top-2 in ordered-uint domain (per-lane o1 >= o2 on entry).
__device__ __forceinline__ void warp_top2(unsigned& o1, unsigned& o2) {
    unsigned r1  = __reduce_max_sync(0xFFFFFFFFu, o1);
    unsigned bal = __ballot_sync(0xFFFFFFFFu, o1 == r1);
    unsigned u   = (o1 == r1) ? o2 : o1;
    unsigned r2  = __reduce_max_sync(0xFFFFFFFFu, u);
    if (__popc(bal) > 1) r2 = r1;   // duplicated max across lanes -> t2 == t1
    o1 = r1; o2 = r2;
}

// Branchless exact top-2 of 8 (FMNMX tournament)
__device__ __forceinline__ void top2_8(const float* v, float& t1, float& t2) {
    float m0 = fmaxf(v[0], v[1]), n0 = fminf(v[0], v[1]);
    float m1 = fmaxf(v[2], v[3]), n1 = fminf(v[2], v[3]);
    float m2 = fmaxf(v[4], v[5]), n2 = fminf(v[4], v[5]);
    float m3 = fmaxf(v[6], v[7]), n3 = fminf(v[6], v[7]);
    float a1 = fmaxf(m0, m1), a2 = fmaxf(fminf(m0, m1), fmaxf(n0, n1));
    float b1 = fmaxf(m2, m3), b2 = fmaxf(fminf(m2, m3), fmaxf(n2, n3));
    t1 = fmaxf(a1, b1);
    t2 = fmaxf(fminf(a1, b1), fmaxf(a2, b2));
}

// Exact top-2 of 16 = merge of two top2_8
__device__ __forceinline__ void top2_16(const float* v, float& t1, float& t2) {
    float p1, p2, q1, q2;
    top2_8(v, p1, p2);
    top2_8(v + 8, q1, q2);
    t1 = fmaxf(p1, q1);
    t2 = fmaxf(fminf(p1, q1), fmaxf(p2, q2));
}

// Merge (t1,t2) pair q into accumulator
__device__ __forceinline__ void pair_merge(float& t1, float& t2, float q1, float q2) {
    float mn = fminf(t1, q1);
    t1 = fmaxf(t1, q1);
    t2 = fmaxf(mn, fmaxf(t2, q2));
}

__global__ __launch_bounds__(TPB, 12)
void netsat1_kernel(const float* __restrict__ y1,
                    const float* __restrict__ y2,
                    float* __restrict__ out)
{
    const int row = blockIdx.x;
    const int t   = threadIdx.x;
    const int wid = t >> 5;
    const int lid = t & 31;

    const float4* r1 = reinterpret_cast<const float4*>(y1 + (size_t)row * NCOLS);
    const float4* r2 = reinterpret_cast<const float4*>(y2 + (size_t)row * NCOLS);

    // 4 float4 chunks per array: t, t+64, t+128 always valid (<250); t+192 valid for t<58
    float a[16], b[16];
    const bool c3 = (t < NVEC - 3 * TPB);   // t < 58
    {
        float4 v0 = __ldcs(&r1[t]);
        float4 v1 = __ldcs(&r1[t + TPB]);
        float4 v2 = __ldcs(&r1[t + 2 * TPB]);
        float4 w0 = __ldcs(&r2[t]);
        float4 w1 = __ldcs(&r2[t + TPB]);
        float4 w2 = __ldcs(&r2[t + 2 * TPB]);
        float4 v3, w3;
        if (c3) { v3 = __ldcs(&r1[t + 3 * TPB]); w3 = __ldcs(&r2[t + 3 * TPB]); }
        else    { v3 = make_float4(-FLT_MAX,-FLT_MAX,-FLT_MAX,-FLT_MAX); w3 = v3; }
        a[0]=v0.x; a[1]=v0.y; a[2]=v0.z; a[3]=v0.w;
        a[4]=v1.x; a[5]=v1.y; a[6]=v1.z; a[7]=v1.w;
        a[8]=v2.x; a[9]=v2.y; a[10]=v2.z; a[11]=v2.w;
        a[12]=v3.x; a[13]=v3.y; a[14]=v3.z; a[15]=v3.w;
        b[0]=w0.x; b[1]=w0.y; b[2]=w0.z; b[3]=w0.w;
        b[4]=w1.x; b[5]=w1.y; b[6]=w1.z; b[7]=w1.w;
        b[8]=w2.x; b[9]=w2.y; b[10]=w2.z; b[11]=w2.w;
        b[12]=w3.x; b[13]=w3.y; b[14]=w3.z; b[15]=w3.w;
    }

    // --- Pass 1: per-thread exact top-2 of 16, then warp top-2 ---
    float ta1, ta2, tb1, tb2;
    top2_16(a, ta1, ta2);
    top2_16(b, tb1, tb2);

    unsigned oa1 = ford(ta1), oa2 = ford(ta2);
    unsigned ob1 = ford(tb1), ob2 = ford(tb2);
    warp_top2(oa1, oa2);
    warp_top2(ob1, ob2);

    __shared__ float4 sw[NWARP];
    __shared__ unsigned smax[NWARP];

    if (lid == 0)
        sw[wid] = make_float4(funord(oa1), funord(oa2), funord(ob1), funord(ob2));
    __syncthreads();

    // Merge the 2 warp pairs (redundant in all threads; 8 FMNMX)
    float4 s0 = sw[0], s1 = sw[1];
    float t1_1 = s0.x, t2_1 = s0.y, t1_2 = s0.z, t2_2 = s0.w;
    pair_merge(t1_1, t2_1, s1.x, s1.y);
    pair_merge(t1_2, t2_2, s1.z, s1.w);

    // --- Pass 2 (registers), shifted domain:
    // min(y1-t1_1, y2-t1_2) = min(y1, y2 + d) - t1_1,  d = t1_1 - t1_2
    const float d = t1_1 - t1_2;
    float m = -FLT_MAX;
    #pragma unroll
    for (int k = 0; k < 16; ++k)
        m = fmaxf(m, fminf(a[k], b[k] + d));

    // Fixup iff this thread holds a row-argmax element of either array (cold).
    if ((ta1 == t1_1) || (tb1 == t1_2)) {
        #pragma unroll
        for (int k = 0; k < 16; ++k) {
            if (a[k] == t1_1 || b[k] == t1_2) {
                float loo1 = (a[k] == t1_1) ? t2_1 : t1_1;
                float loo2 = (b[k] == t1_2) ? t2_2 : t1_2;
                m = fmaxf(m, fminf(a[k] - loo1, b[k] - loo2) + t1_1);  // shifted
            }
        }
    }

    // --- Block max reduce of m (2 warps) ---
    unsigned om = __reduce_max_sync(0xFFFFFFFFu, ford(m));
    if (lid == 0) smax[wid] = om;
    __syncthreads();
    if (t == 0)
        out[row] = funord(max(smax[0], smax[1])) - t1_1;   // un-shift
}

extern "C" void kernel_launch(void* const* d_in, const int* in_sizes, int n_in,
                              void* d_out, int out_size)
{
    const float* y1 = (const float*)d_in[0];
    const float* y2 = (const float*)d_in[1];
    float* out = (float*)d_out;

    const int B = in_sizes[0] / NCOLS;   // 16384
    netsat1_kernel<<<B, TPB>>>(y1, y2, out);
}